// round 4
// baseline (speedup 1.0000x reference)
#include <cuda_runtime.h>
#include <cstdint>
#include <cstddef>

// Problem constants (B=4, H=16, S=2048, D=64)
#define S_LEN   2048
#define D_DIM   64
#define BH      64
#define M_BLK   16          // q rows per CTA
#define KT      64          // keys per k-tile
#define NWARPS  8
#define NTHREADS 256

// padded smem strides (floats) chosen for conflict-free fragment loads
#define STRIDE_E 2052       // E a-frag: bank = (4g+t)%32 -> unique
#define STRIDE_K 68         // K b-frag: bank = (4g+t)%32 -> unique
#define STRIDE_V 72         // V b-frag: bank = (8t+g)%32 -> unique

#define E_OFF    0
#define KS_OFF   (E_OFF + M_BLK*STRIDE_E)
#define VS_OFF   (KS_OFF + KT*STRIDE_K)
#define QS_OFF   (VS_OFF + KT*STRIDE_V)
#define INV_OFF  (QS_OFF + M_BLK*D_DIM)
#define MS_OFF_F (INV_OFF + 16)
#define SMEM_FLOATS (MS_OFF_F + 256)
#define SMEM_BYTES  (SMEM_FLOATS * 4)

// mask encoding: 0 = uint8 (1B/elem), 1 = int32 (4B/elem), 2 = float32 (4B/elem)
__device__ int g_mask_kind;

__global__ void detect_mask_kind(const unsigned char* __restrict__ m) {
    __shared__ int s_big, s_off;
    if (threadIdx.x == 0) { s_big = 0; s_off = 0; }
    __syncthreads();
    int big = 0, off = 0;
    for (int base = threadIdx.x * 16; base < 4096; base += 256 * 16) {
        uint4 v = *(const uint4*)(m + base);
        unsigned int w[4] = {v.x, v.y, v.z, v.w};
#pragma unroll
        for (int j = 0; j < 4; j++) {
#pragma unroll
            for (int b = 0; b < 4; b++) {
                unsigned int byte = (w[j] >> (8 * b)) & 0xFFu;
                if (byte > 1u) big = 1;
                if (byte != 0u && (((base + 4 * j + b) & 3) != 0)) off = 1;
            }
        }
    }
    if (big) atomicOr(&s_big, 1);
    if (off) atomicOr(&s_off, 1);
    __syncthreads();
    if (threadIdx.x == 0)
        g_mask_kind = s_big ? 2 : (s_off ? 0 : 1);
}

__device__ __forceinline__ float tf32r(float x) {
    uint32_t u;
    asm("cvt.rna.tf32.f32 %0, %1;" : "=r"(u) : "f"(x));
    return __uint_as_float(u);
}

__device__ __forceinline__ void mma_tf32(float c[4],
                                         uint32_t a0, uint32_t a1, uint32_t a2, uint32_t a3,
                                         uint32_t b0, uint32_t b1) {
    asm volatile(
        "mma.sync.aligned.m16n8k8.row.col.f32.tf32.tf32.f32 "
        "{%0,%1,%2,%3}, {%4,%5,%6,%7}, {%8,%9}, {%0,%1,%2,%3};\n"
        : "+f"(c[0]), "+f"(c[1]), "+f"(c[2]), "+f"(c[3])
        : "r"(a0), "r"(a1), "r"(a2), "r"(a3), "r"(b0), "r"(b1));
}

__global__ void __launch_bounds__(NTHREADS, 1)
sdpa_kernel(const float* __restrict__ Q, const float* __restrict__ K,
            const float* __restrict__ V, const unsigned char* __restrict__ M,
            float* __restrict__ ctx, float* __restrict__ attn) {
    extern __shared__ float sm[];
    float* E  = sm + E_OFF;
    float* Ks = sm + KS_OFF;
    float* Vs = sm + VS_OFF;
    float* Qs = sm + QS_OFF;
    float* inv = sm + INV_OFF;
    unsigned char* Ms = (unsigned char*)(sm + MS_OFF_F);

    const int qb = blockIdx.x;       // 0..127 (q block within head)
    const int bh = blockIdx.y;       // 0..63  (batch*head)
    const int q0 = qb * M_BLK;

    const float* Qp = Q + ((size_t)bh * S_LEN + q0) * D_DIM;
    const float* Kp = K + (size_t)bh * S_LEN * D_DIM;
    const float* Vp = V + (size_t)bh * S_LEN * D_DIM;
    const size_t mrow0 = (size_t)bh * S_LEN + q0;   // first mask row index

    const int tid  = threadIdx.x;
    const int warp = tid >> 5;
    const int lane = tid & 31;
    const int g = lane >> 2;   // groupID
    const int t = lane & 3;    // thread in group
    const int n0 = warp * 8;   // this warp's 8-wide column block

    const int mkind = g_mask_kind;

    // ---- load Q block (tf32-rounded) ----
    for (int i = tid; i < M_BLK * D_DIM; i += NTHREADS)
        Qs[i] = tf32r(Qp[i]);
    __syncthreads();

    // A fragments of Q for all 8 d-steps (persist in registers)
    uint32_t qa[8][4];
#pragma unroll
    for (int s = 0; s < 8; s++) {
        qa[s][0] = __float_as_uint(Qs[g * D_DIM + 8 * s + t]);
        qa[s][1] = __float_as_uint(Qs[(g + 8) * D_DIM + 8 * s + t]);
        qa[s][2] = __float_as_uint(Qs[g * D_DIM + 8 * s + t + 4]);
        qa[s][3] = __float_as_uint(Qs[(g + 8) * D_DIM + 8 * s + t + 4]);
    }

    float acc[4] = {0.f, 0.f, 0.f, 0.f};   // PV accumulator (16 x 8 per warp)

    for (int kt = 0; kt < S_LEN / KT; kt++) {
        const int ko = kt * KT;
        __syncthreads();   // previous iter's PV reads of Vs done before overwrite

        // ---- load K/V tiles (tf32-rounded) ----
        for (int i = tid; i < KT * D_DIM; i += NTHREADS) {
            int r = i >> 6, c = i & 63;
            size_t go = (size_t)(ko + r) * D_DIM + c;
            Ks[r * STRIDE_K + c] = tf32r(Kp[go]);
            Vs[r * STRIDE_V + c] = tf32r(Vp[go]);
        }
        // ---- load mask tile (dtype-robust) ----
        {
            int r = tid >> 4;             // 0..15
            int c = (tid & 15) * 4;       // 0..60
            size_t eoff = (mrow0 + r) * S_LEN + ko + c;   // element offset
            uchar4 mv;
            if (mkind == 1) {
                int4 v = *(const int4*)((const int*)M + eoff);
                mv = make_uchar4(v.x != 0, v.y != 0, v.z != 0, v.w != 0);
            } else if (mkind == 2) {
                float4 v = *(const float4*)((const float*)M + eoff);
                mv = make_uchar4(v.x != 0.f, v.y != 0.f, v.z != 0.f, v.w != 0.f);
            } else {
                mv = *(const uchar4*)(M + eoff);
            }
            *(uchar4*)(Ms + r * 64 + c) = mv;
        }
        __syncthreads();

        // ---- QK^T: 16 x 8 per warp over 8 d-steps ----
        float c4[4] = {0.f, 0.f, 0.f, 0.f};
#pragma unroll
        for (int s = 0; s < 8; s++) {
            uint32_t b0 = __float_as_uint(Ks[(n0 + g) * STRIDE_K + 8 * s + t]);
            uint32_t b1 = __float_as_uint(Ks[(n0 + g) * STRIDE_K + 8 * s + t + 4]);
            mma_tf32(c4, qa[s][0], qa[s][1], qa[s][2], qa[s][3], b0, b1);
        }

        // ---- scale, mask, exp; write e to smem E ----
        const float scale = 0.125f;
        int col = n0 + 2 * t;
        float e00 = Ms[g * 64 + col]           ? 0.f : __expf(c4[0] * scale);
        float e01 = Ms[g * 64 + col + 1]       ? 0.f : __expf(c4[1] * scale);
        float e10 = Ms[(g + 8) * 64 + col]     ? 0.f : __expf(c4[2] * scale);
        float e11 = Ms[(g + 8) * 64 + col + 1] ? 0.f : __expf(c4[3] * scale);
        *(float2*)&E[g * STRIDE_E + ko + col]       = make_float2(e00, e01);
        *(float2*)&E[(g + 8) * STRIDE_E + ko + col] = make_float2(e10, e11);
        __syncthreads();

        // ---- PV: acc += e_tile @ V_tile (A from E, B from Vs) ----
#pragma unroll
        for (int s = 0; s < 8; s++) {
            uint32_t a0 = __float_as_uint(E[g * STRIDE_E + ko + 8 * s + t]);
            uint32_t a1 = __float_as_uint(E[(g + 8) * STRIDE_E + ko + 8 * s + t]);
            uint32_t a2 = __float_as_uint(E[g * STRIDE_E + ko + 8 * s + t + 4]);
            uint32_t a3 = __float_as_uint(E[(g + 8) * STRIDE_E + ko + 8 * s + t + 4]);
            uint32_t b0 = __float_as_uint(Vs[(8 * s + t) * STRIDE_V + n0 + g]);
            uint32_t b1 = __float_as_uint(Vs[(8 * s + t + 4) * STRIDE_V + n0 + g]);
            mma_tf32(acc, a0, a1, a2, a3, b0, b1);
        }
    }
    __syncthreads();

    // ---- rowsums -> 1/Z (each warp reduces 2 rows) ----
    for (int r = warp * 2; r < warp * 2 + 2; r++) {
        float s = 0.f;
        for (int c = lane; c < S_LEN; c += 32)
            s += E[r * STRIDE_E + c];
#pragma unroll
        for (int o = 16; o; o >>= 1)
            s += __shfl_xor_sync(0xFFFFFFFFu, s, o);
        if (lane == 0) inv[r] = 1.f / s;
    }
    __syncthreads();

    // ---- write context = acc / Z ----
    {
        float* cp = ctx + ((size_t)bh * S_LEN + q0) * D_DIM;
        int col = n0 + 2 * t;
        float i0 = inv[g], i1 = inv[g + 8];
        *(float2*)&cp[g * D_DIM + col]       = make_float2(acc[0] * i0, acc[1] * i0);
        *(float2*)&cp[(g + 8) * D_DIM + col] = make_float2(acc[2] * i1, acc[3] * i1);
    }

    // ---- write attn = e / Z (streaming float4) ----
    float* ap = attn + ((size_t)bh * S_LEN + q0) * S_LEN;
    for (int r = 0; r < M_BLK; r++) {
        float iv = inv[r];
        for (int c = tid * 4; c < S_LEN; c += NTHREADS * 4) {
            float4 v = *(float4*)&E[r * STRIDE_E + c];
            v.x *= iv; v.y *= iv; v.z *= iv; v.w *= iv;
            *(float4*)&ap[(size_t)r * S_LEN + c] = v;
        }
    }
}

extern "C" void kernel_launch(void* const* d_in, const int* in_sizes, int n_in,
                              void* d_out, int out_size) {
    const float* Q = (const float*)d_in[0];
    const float* K = (const float*)d_in[1];
    const float* V = (const float*)d_in[2];
    const unsigned char* M = (const unsigned char*)d_in[3];

    float* ctx  = (float*)d_out;                                   // [B,H,S,64]
    float* attn = ctx + (size_t)BH * S_LEN * D_DIM;                // [B,H,S,S]

    cudaFuncSetAttribute(sdpa_kernel,
                         cudaFuncAttributeMaxDynamicSharedMemorySize, SMEM_BYTES);

    detect_mask_kind<<<1, 256>>>(M);

    dim3 grid(S_LEN / M_BLK, BH);   // x = q-blocks (fast) -> K/V L2 reuse per head
    sdpa_kernel<<<grid, NTHREADS, SMEM_BYTES>>>(Q, K, V, M, ctx, attn);
}

// round 5
// speedup vs baseline: 3.0891x; 3.0891x over previous
#include <cuda_runtime.h>
#include <cstdint>
#include <cstddef>

// Problem constants (B=4, H=16, S=2048, D=64)
#define S_LEN   2048
#define D_DIM   64
#define BH      64
#define M_BLK   64          // q rows per CTA
#define KT      64          // keys per k-tile
#define NT      (S_LEN/KT)  // 32 iterations
#define NTHREADS 256

// padded smem strides (floats), conflict-free for fragment access patterns
#define STRIDE_Q 68
#define STRIDE_K 68
#define STRIDE_V 72
#define STRIDE_E 68

// smem layout (float offsets)
#define QS_OFF 0
#define KS_OFF (QS_OFF + M_BLK*STRIDE_Q)            // Qs: 4352
#define VS_OFF (KS_OFF + 2*KT*STRIDE_K)             // Ks x2: 8704
#define ES_OFF (VS_OFF + 2*KT*STRIDE_V)             // Vs x2: 9216
#define SMEM_FLOATS (ES_OFF + M_BLK*STRIDE_E)       // Es: 4352  -> 26624
#define SMEM_BYTES  (SMEM_FLOATS*4)                 // 106496 B -> 2 CTAs/SM

__device__ int   g_mask_kind;                 // 0 = 1B/elem, 1/2 = 4B/elem
__device__ float g_inv_arr[BH*S_LEN];         // per-row 1/Z for normalize pass

__global__ void detect_mask_kind(const unsigned char* __restrict__ m) {
    __shared__ int s_big, s_off;
    if (threadIdx.x == 0) { s_big = 0; s_off = 0; }
    __syncthreads();
    int big = 0, off = 0;
    for (int base = threadIdx.x * 16; base < 4096; base += 256 * 16) {
        uint4 v = *(const uint4*)(m + base);
        unsigned int w[4] = {v.x, v.y, v.z, v.w};
#pragma unroll
        for (int j = 0; j < 4; j++)
#pragma unroll
            for (int b = 0; b < 4; b++) {
                unsigned int byte = (w[j] >> (8 * b)) & 0xFFu;
                if (byte > 1u) big = 1;
                if (byte != 0u && (((base + 4 * j + b) & 3) != 0)) off = 1;
            }
    }
    if (big) atomicOr(&s_big, 1);
    if (off) atomicOr(&s_off, 1);
    __syncthreads();
    if (threadIdx.x == 0) g_mask_kind = s_big ? 2 : (s_off ? 0 : 1);
}

__device__ __forceinline__ float tf32r(float x) {
    uint32_t u;
    asm("cvt.rna.tf32.f32 %0, %1;" : "=r"(u) : "f"(x));
    return __uint_as_float(u);
}

__device__ __forceinline__ void mma_tf32(float c[4],
                                         uint32_t a0, uint32_t a1, uint32_t a2, uint32_t a3,
                                         uint32_t b0, uint32_t b1) {
    asm volatile(
        "mma.sync.aligned.m16n8k8.row.col.f32.tf32.tf32.f32 "
        "{%0,%1,%2,%3}, {%4,%5,%6,%7}, {%8,%9}, {%0,%1,%2,%3};\n"
        : "+f"(c[0]), "+f"(c[1]), "+f"(c[2]), "+f"(c[3])
        : "r"(a0), "r"(a1), "r"(a2), "r"(a3), "r"(b0), "r"(b1));
}

__device__ __forceinline__ void cp16(void* smem_dst, const void* gmem_src) {
    unsigned a = (unsigned)__cvta_generic_to_shared(smem_dst);
    asm volatile("cp.async.cg.shared.global [%0], [%1], 16;\n" :: "r"(a), "l"(gmem_src));
}

__global__ void __launch_bounds__(NTHREADS, 2)
sdpa_main(const float* __restrict__ Q, const float* __restrict__ K,
          const float* __restrict__ V, const unsigned char* __restrict__ M,
          float* __restrict__ ctx, float* __restrict__ attn) {
    extern __shared__ float sm[];
    float* Qs = sm + QS_OFF;
    float* Ks = sm + KS_OFF;
    float* Vs = sm + VS_OFF;
    float* Es = sm + ES_OFF;

    const int qb = blockIdx.x;          // 0..31
    const int bh = blockIdx.y;          // 0..63
    const int q0 = qb * M_BLK;

    const float* Qp = Q + ((size_t)bh * S_LEN + q0) * D_DIM;
    const float* Kp = K + (size_t)bh * S_LEN * D_DIM;
    const float* Vp = V + (size_t)bh * S_LEN * D_DIM;
    const size_t mrow0 = (size_t)bh * S_LEN + q0;

    const int tid  = threadIdx.x;
    const int warp = tid >> 5;
    const int lane = tid & 31;
    const int g = lane >> 2;
    const int t = lane & 3;
    const int n0 = warp * 8;
    const bool m4 = (g_mask_kind != 0);

    // ---- Qs fill (tf32-rounded) ----
    for (int i = tid; i < M_BLK * D_DIM; i += NTHREADS) {
        int r = i >> 6, c = i & 63;
        Qs[r * STRIDE_Q + c] = tf32r(Qp[i]);
    }

    // ---- prefetch kt=0 ----
    {
        float* kd = Ks; float* vd = Vs;
#pragma unroll
        for (int j = 0; j < 4; j++) {
            int i = tid + j * NTHREADS;              // 0..1023
            int r = i >> 4, c = (i & 15) * 4;
            cp16(&kd[r * STRIDE_K + c], Kp + r * D_DIM + c);
            cp16(&vd[r * STRIDE_V + c], Vp + r * D_DIM + c);
        }
    }
    asm volatile("cp.async.commit_group;\n");

    float acc[4][4] = {};
    float rs[4][2]  = {};

    for (int kt = 0; kt < NT; kt++) {
        const int cur = kt & 1;
        const int ko  = kt * KT;
        __syncthreads();                 // (A) prev iter done with bufs; Qs ready
        if (kt + 1 < NT) {
            float* kd = Ks + (cur ^ 1) * KT * STRIDE_K;
            float* vd = Vs + (cur ^ 1) * KT * STRIDE_V;
            const float* ks = Kp + (size_t)(ko + KT) * D_DIM;
            const float* vs = Vp + (size_t)(ko + KT) * D_DIM;
#pragma unroll
            for (int j = 0; j < 4; j++) {
                int i = tid + j * NTHREADS;
                int r = i >> 4, c = (i & 15) * 4;
                cp16(&kd[r * STRIDE_K + c], ks + r * D_DIM + c);
                cp16(&vd[r * STRIDE_V + c], vs + r * D_DIM + c);
            }
        }
        asm volatile("cp.async.commit_group;\n");
        asm volatile("cp.async.wait_group 1;\n");
        __syncthreads();                 // (B) cur tile visible

        // ---- mask -> registers (issued before QK so DRAM latency hides) ----
        unsigned mf[4][4];
        if (m4) {
            const int* mp = (const int*)M;
#pragma unroll
            for (int mt = 0; mt < 4; mt++) {
                int2 a = *(const int2*)(mp + (mrow0 + 16 * mt + g) * S_LEN + ko + n0 + 2 * t);
                int2 b = *(const int2*)(mp + (mrow0 + 16 * mt + g + 8) * S_LEN + ko + n0 + 2 * t);
                mf[mt][0] = a.x; mf[mt][1] = a.y; mf[mt][2] = b.x; mf[mt][3] = b.y;
            }
        } else {
#pragma unroll
            for (int mt = 0; mt < 4; mt++) {
                const unsigned char* pa = M + (mrow0 + 16 * mt + g) * S_LEN + ko + n0 + 2 * t;
                const unsigned char* pb = M + (mrow0 + 16 * mt + g + 8) * S_LEN + ko + n0 + 2 * t;
                mf[mt][0] = pa[0]; mf[mt][1] = pa[1]; mf[mt][2] = pb[0]; mf[mt][3] = pb[1];
            }
        }

        const float* Kb = Ks + cur * KT * STRIDE_K;
        const float* Vb = Vs + cur * KT * STRIDE_V;

        // ---- QK^T: 64x64 tile, 4 m-frags x 8 d-steps per warp ----
        float c4[4][4] = {};
#pragma unroll
        for (int s = 0; s < 8; s++) {
            uint32_t b0 = __float_as_uint(tf32r(Kb[(n0 + g) * STRIDE_K + 8 * s + t]));
            uint32_t b1 = __float_as_uint(tf32r(Kb[(n0 + g) * STRIDE_K + 8 * s + t + 4]));
#pragma unroll
            for (int mt = 0; mt < 4; mt++) {
                int r0 = (16 * mt + g) * STRIDE_Q, r1 = (16 * mt + g + 8) * STRIDE_Q;
                uint32_t a0 = __float_as_uint(Qs[r0 + 8 * s + t]);
                uint32_t a1 = __float_as_uint(Qs[r1 + 8 * s + t]);
                uint32_t a2 = __float_as_uint(Qs[r0 + 8 * s + t + 4]);
                uint32_t a3 = __float_as_uint(Qs[r1 + 8 * s + t + 4]);
                mma_tf32(c4[mt], a0, a1, a2, a3, b0, b1);
            }
        }

        // ---- e = mask ? 0 : exp(s/8); write Es; accumulate rowsums ----
        const float scale = 0.125f;
        const int col = n0 + 2 * t;
#pragma unroll
        for (int mt = 0; mt < 4; mt++) {
            float e00 = mf[mt][0] ? 0.f : __expf(c4[mt][0] * scale);
            float e01 = mf[mt][1] ? 0.f : __expf(c4[mt][1] * scale);
            float e10 = mf[mt][2] ? 0.f : __expf(c4[mt][2] * scale);
            float e11 = mf[mt][3] ? 0.f : __expf(c4[mt][3] * scale);
            *(float2*)&Es[(16 * mt + g) * STRIDE_E + col]     = make_float2(e00, e01);
            *(float2*)&Es[(16 * mt + g + 8) * STRIDE_E + col] = make_float2(e10, e11);
            rs[mt][0] += e00 + e01;
            rs[mt][1] += e10 + e11;
        }
        __syncthreads();                 // (C) Es complete

        // ---- stream unnormalized e tile to GMEM attn (coalesced 256B rows) ----
        {
            int r = tid >> 2, c0 = (tid & 3) * 16;
            float* dst = attn + (mrow0 + r) * S_LEN + ko + c0;
#pragma unroll
            for (int j = 0; j < 4; j++)
                *(float4*)(dst + 4 * j) = *(float4*)&Es[r * STRIDE_E + c0 + 4 * j];
        }

        // ---- PV: acc += e @ V ----
#pragma unroll
        for (int s = 0; s < 8; s++) {
            uint32_t b0 = __float_as_uint(tf32r(Vb[(8 * s + t) * STRIDE_V + n0 + g]));
            uint32_t b1 = __float_as_uint(tf32r(Vb[(8 * s + t + 4) * STRIDE_V + n0 + g]));
#pragma unroll
            for (int mt = 0; mt < 4; mt++) {
                int r0 = (16 * mt + g) * STRIDE_E, r1 = (16 * mt + g + 8) * STRIDE_E;
                uint32_t a0 = __float_as_uint(Es[r0 + 8 * s + t]);
                uint32_t a1 = __float_as_uint(Es[r1 + 8 * s + t]);
                uint32_t a2 = __float_as_uint(Es[r0 + 8 * s + t + 4]);
                uint32_t a3 = __float_as_uint(Es[r1 + 8 * s + t + 4]);
                mma_tf32(acc[mt], a0, a1, a2, a3, b0, b1);
            }
        }
    }

    __syncthreads();                     // Es free; reuse for reductions
    float* Rs   = Es;                    // [8 warps][64 rows]
    float* invs = Es + 512;

#pragma unroll
    for (int mt = 0; mt < 4; mt++) {
        float s0 = rs[mt][0], s1 = rs[mt][1];
        s0 += __shfl_xor_sync(0xFFFFFFFFu, s0, 1);
        s0 += __shfl_xor_sync(0xFFFFFFFFu, s0, 2);
        s1 += __shfl_xor_sync(0xFFFFFFFFu, s1, 1);
        s1 += __shfl_xor_sync(0xFFFFFFFFu, s1, 2);
        if (t == 0) {
            Rs[warp * 64 + 16 * mt + g]     = s0;
            Rs[warp * 64 + 16 * mt + g + 8] = s1;
        }
    }
    __syncthreads();
    if (tid < 64) {
        float s = 0.f;
#pragma unroll
        for (int w = 0; w < 8; w++) s += Rs[w * 64 + tid];
        float iv = 1.f / s;
        invs[tid] = iv;
        g_inv_arr[mrow0 + tid] = iv;
    }
    __syncthreads();

    // ---- context = acc / Z ----
    float* cp = ctx + mrow0 * D_DIM;
    const int col = n0 + 2 * t;
#pragma unroll
    for (int mt = 0; mt < 4; mt++) {
        float i0 = invs[16 * mt + g], i1 = invs[16 * mt + g + 8];
        *(float2*)&cp[(16 * mt + g) * D_DIM + col]     = make_float2(acc[mt][0] * i0, acc[mt][1] * i0);
        *(float2*)&cp[(16 * mt + g + 8) * D_DIM + col] = make_float2(acc[mt][2] * i1, acc[mt][3] * i1);
    }
}

// second pass: attn[row, :] *= 1/Z[row]   (512 float4 per row)
__global__ void normalize_attn(float* __restrict__ attn) {
    const size_t n4 = (size_t)BH * S_LEN * S_LEN / 4;
    size_t i = (size_t)blockIdx.x * blockDim.x + threadIdx.x;
    const size_t stride = (size_t)gridDim.x * blockDim.x;
    float4* a4 = (float4*)attn;
    for (; i < n4; i += stride) {
        float iv = g_inv_arr[i >> 9];
        float4 v = a4[i];
        v.x *= iv; v.y *= iv; v.z *= iv; v.w *= iv;
        a4[i] = v;
    }
}

extern "C" void kernel_launch(void* const* d_in, const int* in_sizes, int n_in,
                              void* d_out, int out_size) {
    const float* Q = (const float*)d_in[0];
    const float* K = (const float*)d_in[1];
    const float* V = (const float*)d_in[2];
    const unsigned char* M = (const unsigned char*)d_in[3];

    float* ctx  = (float*)d_out;                          // [B,H,S,64]
    float* attn = ctx + (size_t)BH * S_LEN * D_DIM;       // [B,H,S,S]

    cudaFuncSetAttribute(sdpa_main,
                         cudaFuncAttributeMaxDynamicSharedMemorySize, SMEM_BYTES);

    detect_mask_kind<<<1, 256>>>(M);

    dim3 grid(S_LEN / M_BLK, BH);                         // 32 x 64 = 2048 CTAs
    sdpa_main<<<grid, NTHREADS, SMEM_BYTES>>>(Q, K, V, M, ctx, attn);

    normalize_attn<<<8192, 256>>>(attn);
}

// round 7
// speedup vs baseline: 5.3108x; 1.7192x over previous
#include <cuda_runtime.h>
#include <cuda_fp16.h>
#include <cstdint>
#include <cstddef>

// Problem constants (B=4, H=16, S=2048, D=64)
#define S_LEN   2048
#define D_DIM   64
#define BH      64
#define M_BLK   128
#define KT      64
#define NT      (S_LEN/KT)
#define NTHREADS 256

#define QSH     72                    // halves per row (36 words: 4g+t bank spread)
#define TILE_H  (KT*QSH)              // 4608 halves per K/V tile

// smem half offsets
#define QS_OFF  0
#define KH_OFF  (M_BLK*QSH)           // 9216
#define VH_OFF  (KH_OFF + 2*TILE_H)   // 18432
#define SMEM_HALVES (VH_OFF + 2*TILE_H)
#define SMEM_BYTES  (SMEM_HALVES*2)   // 55296 B -> 2 CTAs/SM

__device__ __half g_Kh[(size_t)BH*S_LEN*D_DIM];   // [bh][key][d] fp16
__device__ __half g_Vt[(size_t)BH*S_LEN*D_DIM];   // [bh][kt][d][key] fp16 (per-tile transposed)
__device__ float  g_inv_arr[BH*S_LEN];
__device__ int    g_mask_kind;        // 0 = 1B/elem, 1 = 4B/elem

__global__ void detect_mask_kind(const unsigned char* __restrict__ m) {
    __shared__ int s_big, s_off;
    if (threadIdx.x == 0) { s_big = 0; s_off = 0; }
    __syncthreads();
    int big = 0, off = 0;
    for (int base = threadIdx.x * 16; base < 4096; base += 256 * 16) {
        uint4 v = *(const uint4*)(m + base);
        unsigned int w[4] = {v.x, v.y, v.z, v.w};
#pragma unroll
        for (int j = 0; j < 4; j++)
#pragma unroll
            for (int b = 0; b < 4; b++) {
                unsigned int byte = (w[j] >> (8 * b)) & 0xFFu;
                if (byte > 1u) big = 1;
                if (byte != 0u && (((base + 4 * j + b) & 3) != 0)) off = 1;
            }
    }
    if (big) atomicOr(&s_big, 1);
    if (off) atomicOr(&s_off, 1);
    __syncthreads();
    if (threadIdx.x == 0) g_mask_kind = (s_big || !s_off) ? 1 : 0;
}

// K -> fp16, elementwise (layout unchanged)
__global__ void convert_k(const float* __restrict__ K) {
    const size_t n4 = (size_t)BH * S_LEN * D_DIM / 4;
    size_t i = (size_t)blockIdx.x * blockDim.x + threadIdx.x;
    const size_t stride = (size_t)gridDim.x * blockDim.x;
    for (; i < n4; i += stride) {
        float4 v = ((const float4*)K)[i];
        ((__half2*)g_Kh)[2*i]   = __floats2half2_rn(v.x, v.y);
        ((__half2*)g_Kh)[2*i+1] = __floats2half2_rn(v.z, v.w);
    }
}

// V -> fp16, transposed within each 64-key tile: g_Vt[bh][kt][d][k]
__global__ void transpose_v(const float* __restrict__ V) {
    __shared__ float vs[KT][D_DIM + 1];
    const int kt = blockIdx.x, bh = blockIdx.y;
    const float* src = V + ((size_t)bh * S_LEN + kt * KT) * D_DIM;
    const int tid = threadIdx.x;
    for (int i = tid * 4; i < KT * D_DIM; i += NTHREADS * 4) {
        float4 v = *(const float4*)(src + i);
        int r = i >> 6, c = i & 63;
        vs[r][c] = v.x; vs[r][c+1] = v.y; vs[r][c+2] = v.z; vs[r][c+3] = v.w;
    }
    __syncthreads();
    __half* dst = g_Vt + ((size_t)bh * NT + kt) * (KT * D_DIM);
    for (int w = tid; w < KT * D_DIM / 2; w += NTHREADS) {
        int d = w >> 5, kp = w & 31;       // halves [d*64 + 2kp, +1] = keys (2kp, 2kp+1)
        ((__half2*)dst)[w] = __floats2half2_rn(vs[2*kp][d], vs[2*kp+1][d]);
    }
}

__device__ __forceinline__ void mma_f16(float c[4],
                                        uint32_t a0, uint32_t a1, uint32_t a2, uint32_t a3,
                                        uint32_t b0, uint32_t b1) {
    asm volatile(
        "mma.sync.aligned.m16n8k16.row.col.f32.f16.f16.f32 "
        "{%0,%1,%2,%3}, {%4,%5,%6,%7}, {%8,%9}, {%0,%1,%2,%3};\n"
        : "+f"(c[0]), "+f"(c[1]), "+f"(c[2]), "+f"(c[3])
        : "r"(a0), "r"(a1), "r"(a2), "r"(a3), "r"(b0), "r"(b1));
}

__device__ __forceinline__ uint32_t pack_h2(float lo, float hi) {
    __half2 h = __floats2half2_rn(lo, hi);
    return *(uint32_t*)&h;
}

__device__ __forceinline__ void cp16(void* smem_dst, const void* gmem_src) {
    unsigned a = (unsigned)__cvta_generic_to_shared(smem_dst);
    asm volatile("cp.async.cg.shared.global [%0], [%1], 16;\n" :: "r"(a), "l"(gmem_src));
}

__global__ void __launch_bounds__(NTHREADS, 2)
sdpa_main(const float* __restrict__ Q, const unsigned char* __restrict__ M,
          float* __restrict__ ctx, float* __restrict__ attn) {
    extern __shared__ __half smh[];
    __half* Qs = smh + QS_OFF;
    __half* Kh = smh + KH_OFF;
    __half* Vh = smh + VH_OFF;

    const int qb = blockIdx.x;            // 0..15
    const int bh = blockIdx.y;            // 0..63
    const size_t mrow0 = (size_t)bh * S_LEN + qb * M_BLK;

    const int tid = threadIdx.x, warp = tid >> 5, lane = tid & 31;
    const int g = lane >> 2, t = lane & 3;
    const int r0 = 16 * warp;             // this warp's first q-row in CTA tile
    const bool m4 = (g_mask_kind != 0);

    // ---- stage Q as fp16 in smem ----
    const float* Qp = Q + mrow0 * D_DIM;
    for (int i = tid; i < M_BLK * D_DIM / 2; i += NTHREADS) {
        float2 v = *(const float2*)(Qp + 2 * i);
        int e = 2 * i, r = e >> 6, c = e & 63;
        *(__half2*)&Qs[r * QSH + c] = __floats2half2_rn(v.x, v.y);
    }

    // ---- prefetch kt=0 K/V tiles (fp16, 8 KB each) ----
    const __half* gK = g_Kh + (size_t)bh * S_LEN * D_DIM;
    const __half* gV = g_Vt + (size_t)bh * S_LEN * D_DIM;
#pragma unroll
    for (int j = 0; j < 2; j++) {
        int c = tid + j * NTHREADS;       // 0..511
        int row = c >> 3, off = (c & 7) * 8;
        cp16(&Kh[row * QSH + off], gK + row * D_DIM + off);
        cp16(&Vh[row * QSH + off], gV + row * D_DIM + off);
    }
    asm volatile("cp.async.commit_group;\n");

    float acc[8][4] = {};
    float rs0 = 0.f, rs1 = 0.f;

    for (int kt = 0; kt < NT; kt++) {
        const int cur = kt & 1, ko = kt * KT;
        __syncthreads();                  // (A) prev iter done with buffer cur^1
        if (kt + 1 < NT) {
            __half* kd = Kh + (cur ^ 1) * TILE_H;
            __half* vd = Vh + (cur ^ 1) * TILE_H;
            const __half* ks = gK + (size_t)(ko + KT) * D_DIM;
            const __half* vsrc = gV + (size_t)(ko + KT) * D_DIM;
#pragma unroll
            for (int j = 0; j < 2; j++) {
                int c = tid + j * NTHREADS;
                int row = c >> 3, off = (c & 7) * 8;
                cp16(&kd[row * QSH + off], ks + row * D_DIM + off);
                cp16(&vd[row * QSH + off], vsrc + row * D_DIM + off);
            }
        }
        asm volatile("cp.async.commit_group;\n");
        asm volatile("cp.async.wait_group 1;\n");
        __syncthreads();                  // (B) cur tile visible

        // ---- mask -> registers (consumed after QK; latency hidden) ----
        unsigned ax[8], ay[8], bx[8], by[8];
        {
            const size_t ra = (mrow0 + r0 + g) * S_LEN + ko + 2 * t;
            const size_t rb = ra + 8 * S_LEN;
            if (m4) {
#pragma unroll
                for (int nb = 0; nb < 8; nb++) {
                    int2 a = __ldg((const int2*)((const int*)M + ra + 8 * nb));
                    int2 b = __ldg((const int2*)((const int*)M + rb + 8 * nb));
                    ax[nb] = a.x; ay[nb] = a.y; bx[nb] = b.x; by[nb] = b.y;
                }
            } else {
#pragma unroll
                for (int nb = 0; nb < 8; nb++) {
                    unsigned short a = *(const unsigned short*)(M + ra + 8 * nb);
                    unsigned short b = *(const unsigned short*)(M + rb + 8 * nb);
                    ax[nb] = a & 0xFF; ay[nb] = a >> 8; bx[nb] = b & 0xFF; by[nb] = b >> 8;
                }
            }
        }

        // ---- QK^T: 16x64 per warp, fp16 mma, fp32 scores ----
        float c4[8][4] = {};
        const __half* Kb = Kh + cur * TILE_H;
#pragma unroll
        for (int kc = 0; kc < 4; kc++) {
            uint32_t a0 = *(const uint32_t*)&Qs[(r0 + g)     * QSH + 16 * kc + 2 * t];
            uint32_t a1 = *(const uint32_t*)&Qs[(r0 + g + 8) * QSH + 16 * kc + 2 * t];
            uint32_t a2 = *(const uint32_t*)&Qs[(r0 + g)     * QSH + 16 * kc + 2 * t + 8];
            uint32_t a3 = *(const uint32_t*)&Qs[(r0 + g + 8) * QSH + 16 * kc + 2 * t + 8];
#pragma unroll
            for (int nb = 0; nb < 8; nb++) {
                uint32_t b0 = *(const uint32_t*)&Kb[(8 * nb + g) * QSH + 16 * kc + 2 * t];
                uint32_t b1 = *(const uint32_t*)&Kb[(8 * nb + g) * QSH + 16 * kc + 2 * t + 8];
                mma_f16(c4[nb], a0, a1, a2, a3, b0, b1);
            }
        }

        // ---- mask, exp, rowsum; stream unnormalized e straight to gmem ----
        const float scale = 0.125f;
        float* apa = attn + (mrow0 + r0 + g) * S_LEN + ko + 2 * t;
        float* apb = apa + 8 * S_LEN;
#pragma unroll
        for (int nb = 0; nb < 8; nb++) {
            float e0 = ax[nb] ? 0.f : __expf(c4[nb][0] * scale);
            float e1 = ay[nb] ? 0.f : __expf(c4[nb][1] * scale);
            float e2 = bx[nb] ? 0.f : __expf(c4[nb][2] * scale);
            float e3 = by[nb] ? 0.f : __expf(c4[nb][3] * scale);
            c4[nb][0] = e0; c4[nb][1] = e1; c4[nb][2] = e2; c4[nb][3] = e3;
            rs0 += e0 + e1; rs1 += e2 + e3;
            *(float2*)(apa + 8 * nb) = make_float2(e0, e1);
            *(float2*)(apb + 8 * nb) = make_float2(e2, e3);
        }

        // ---- PV: C-frag(e) == A-frag layout after f16x2 pack; zero smem traffic ----
        const __half* Vb = Vh + cur * TILE_H;
#pragma unroll
        for (int kc = 0; kc < 4; kc++) {
            uint32_t p0 = pack_h2(c4[2*kc][0],   c4[2*kc][1]);
            uint32_t p1 = pack_h2(c4[2*kc][2],   c4[2*kc][3]);
            uint32_t p2 = pack_h2(c4[2*kc+1][0], c4[2*kc+1][1]);
            uint32_t p3 = pack_h2(c4[2*kc+1][2], c4[2*kc+1][3]);
#pragma unroll
            for (int db = 0; db < 8; db++) {
                uint32_t b0 = *(const uint32_t*)&Vb[(8 * db + g) * QSH + 16 * kc + 2 * t];
                uint32_t b1 = *(const uint32_t*)&Vb[(8 * db + g) * QSH + 16 * kc + 2 * t + 8];
                mma_f16(acc[db], p0, p1, p2, p3, b0, b1);
            }
        }
    }

    // ---- rowsums: group-of-4 lanes cover the full row ----
    rs0 += __shfl_xor_sync(0xFFFFFFFFu, rs0, 1);
    rs0 += __shfl_xor_sync(0xFFFFFFFFu, rs0, 2);
    rs1 += __shfl_xor_sync(0xFFFFFFFFu, rs1, 1);
    rs1 += __shfl_xor_sync(0xFFFFFFFFu, rs1, 2);
    float iv0 = 1.f / rs0, iv1 = 1.f / rs1;
    if (t == 0) {
        g_inv_arr[mrow0 + r0 + g]     = iv0;
        g_inv_arr[mrow0 + r0 + g + 8] = iv1;
    }

    // ---- context = acc / Z ----
    float* cpa = ctx + (mrow0 + r0 + g) * D_DIM + 2 * t;
    float* cpb = cpa + 8 * D_DIM;
#pragma unroll
    for (int db = 0; db < 8; db++) {
        *(float2*)(cpa + 8 * db) = make_float2(acc[db][0] * iv0, acc[db][1] * iv0);
        *(float2*)(cpb + 8 * db) = make_float2(acc[db][2] * iv1, acc[db][3] * iv1);
    }
}

// second pass: attn[row, :] *= 1/Z[row]
__global__ void normalize_attn(float* __restrict__ attn) {
    const size_t n4 = (size_t)BH * S_LEN * S_LEN / 4;
    size_t i = (size_t)blockIdx.x * blockDim.x + threadIdx.x;
    const size_t stride = (size_t)gridDim.x * blockDim.x;
    float4* a4 = (float4*)attn;
    for (; i < n4; i += stride) {
        float iv = g_inv_arr[i >> 9];
        float4 v = a4[i];
        v.x *= iv; v.y *= iv; v.z *= iv; v.w *= iv;
        a4[i] = v;
    }
}

extern "C" void kernel_launch(void* const* d_in, const int* in_sizes, int n_in,
                              void* d_out, int out_size) {
    const float* Q = (const float*)d_in[0];
    const float* K = (const float*)d_in[1];
    const float* V = (const float*)d_in[2];
    const unsigned char* M = (const unsigned char*)d_in[3];

    float* ctx  = (float*)d_out;                          // [B,H,S,64]
    float* attn = ctx + (size_t)BH * S_LEN * D_DIM;       // [B,H,S,S]

    cudaFuncSetAttribute(sdpa_main,
                         cudaFuncAttributeMaxDynamicSharedMemorySize, SMEM_BYTES);

    detect_mask_kind<<<1, 256>>>(M);
    convert_k<<<2048, 256>>>(K);
    transpose_v<<<dim3(NT, BH), 256>>>(V);

    dim3 grid(S_LEN / M_BLK, BH);                         // 16 x 64 = 1024 CTAs
    sdpa_main<<<grid, NTHREADS, SMEM_BYTES>>>(Q, M, ctx, attn);

    normalize_attn<<<8192, 256>>>(attn);
}

// round 8
// speedup vs baseline: 5.4886x; 1.0335x over previous
#include <cuda_runtime.h>
#include <cuda_fp16.h>
#include <cstdint>
#include <cstddef>

// Problem constants (B=4, H=16, S=2048, D=64)
#define S_LEN   2048
#define D_DIM   64
#define BH      64
#define M_BLK   128
#define KT      64
#define NT      (S_LEN/KT)
#define NTHREADS 256

#define QSH     72                    // halves per K/V row (36 words, conflict-free frags)
#define TILE_H  (KT*QSH)              // 4608 halves per K/V tile

// smem: K double buffer then V double buffer (halves)
#define KH_OFF  0
#define VH_OFF  (2*TILE_H)
#define SMEM_HALVES (4*TILE_H)        // 18432 halves
#define SMEM_BYTES  (SMEM_HALVES*2)   // 36864 B

__device__ __half   g_Kh[(size_t)BH*S_LEN*D_DIM];     // [bh][key][d] fp16
__device__ __half   g_Vt[(size_t)BH*S_LEN*D_DIM];     // [bh][kt][d][key] fp16
__device__ unsigned g_mbits[(size_t)BH*S_LEN*(S_LEN/32)];        // 32 MB bitmask
__device__ uint32_t g_Eh[(size_t)BH*S_LEN*S_LEN/2];   // 512 MB packed-half2 e scratch
__device__ int      g_mask_kind;      // 0 = 1B/elem, 1 = 4B/elem

__global__ void detect_mask_kind(const unsigned char* __restrict__ m) {
    __shared__ int s_big, s_off;
    if (threadIdx.x == 0) { s_big = 0; s_off = 0; }
    __syncthreads();
    int big = 0, off = 0;
    for (int base = threadIdx.x * 16; base < 4096; base += 256 * 16) {
        uint4 v = *(const uint4*)(m + base);
        unsigned int w[4] = {v.x, v.y, v.z, v.w};
#pragma unroll
        for (int j = 0; j < 4; j++)
#pragma unroll
            for (int b = 0; b < 4; b++) {
                unsigned int byte = (w[j] >> (8 * b)) & 0xFFu;
                if (byte > 1u) big = 1;
                if (byte != 0u && (((base + 4 * j + b) & 3) != 0)) off = 1;
            }
    }
    if (big) atomicOr(&s_big, 1);
    if (off) atomicOr(&s_off, 1);
    __syncthreads();
    if (threadIdx.x == 0) g_mask_kind = (s_big || !s_off) ? 1 : 0;
}

// mask -> 1 bit per element, word i covers elements [32i, 32i+32)
__global__ void mask_bits(const unsigned char* __restrict__ M) {
    const size_t nw = (size_t)BH * S_LEN * (S_LEN / 32);
    const bool k4 = (g_mask_kind != 0);
    size_t i = (size_t)blockIdx.x * blockDim.x + threadIdx.x;
    const size_t stride = (size_t)gridDim.x * blockDim.x;
    for (; i < nw; i += stride) {
        unsigned bits = 0;
        if (k4) {
            const int4* p = (const int4*)M + i * 8;
#pragma unroll
            for (int j = 0; j < 8; j++) {
                int4 v = p[j];
                bits |= (unsigned)(v.x != 0) << (4 * j);
                bits |= (unsigned)(v.y != 0) << (4 * j + 1);
                bits |= (unsigned)(v.z != 0) << (4 * j + 2);
                bits |= (unsigned)(v.w != 0) << (4 * j + 3);
            }
        } else {
            const uint4* p = (const uint4*)M + i * 2;
            uint4 v0 = p[0], v1 = p[1];
            unsigned w[8] = {v0.x, v0.y, v0.z, v0.w, v1.x, v1.y, v1.z, v1.w};
#pragma unroll
            for (int j = 0; j < 8; j++)
#pragma unroll
                for (int b = 0; b < 4; b++)
                    bits |= (unsigned)(((w[j] >> (8 * b)) & 0xFFu) != 0) << (4 * j + b);
        }
        g_mbits[i] = bits;
    }
}

// K -> fp16, elementwise
__global__ void convert_k(const float* __restrict__ K) {
    const size_t n4 = (size_t)BH * S_LEN * D_DIM / 4;
    size_t i = (size_t)blockIdx.x * blockDim.x + threadIdx.x;
    const size_t stride = (size_t)gridDim.x * blockDim.x;
    for (; i < n4; i += stride) {
        float4 v = ((const float4*)K)[i];
        ((__half2*)g_Kh)[2*i]   = __floats2half2_rn(v.x, v.y);
        ((__half2*)g_Kh)[2*i+1] = __floats2half2_rn(v.z, v.w);
    }
}

// V -> fp16, transposed per 64-key tile
__global__ void transpose_v(const float* __restrict__ V) {
    __shared__ float vs[KT][D_DIM + 1];
    const int kt = blockIdx.x, bh = blockIdx.y;
    const float* src = V + ((size_t)bh * S_LEN + kt * KT) * D_DIM;
    const int tid = threadIdx.x;
    for (int i = tid * 4; i < KT * D_DIM; i += NTHREADS * 4) {
        float4 v = *(const float4*)(src + i);
        int r = i >> 6, c = i & 63;
        vs[r][c] = v.x; vs[r][c+1] = v.y; vs[r][c+2] = v.z; vs[r][c+3] = v.w;
    }
    __syncthreads();
    __half* dst = g_Vt + ((size_t)bh * NT + kt) * (KT * D_DIM);
    for (int w = tid; w < KT * D_DIM / 2; w += NTHREADS) {
        int d = w >> 5, kp = w & 31;
        ((__half2*)dst)[w] = __floats2half2_rn(vs[2*kp][d], vs[2*kp+1][d]);
    }
}

__device__ __forceinline__ void mma_f16(float c[4],
                                        uint32_t a0, uint32_t a1, uint32_t a2, uint32_t a3,
                                        uint32_t b0, uint32_t b1) {
    asm volatile(
        "mma.sync.aligned.m16n8k16.row.col.f32.f16.f16.f32 "
        "{%0,%1,%2,%3}, {%4,%5,%6,%7}, {%8,%9}, {%0,%1,%2,%3};\n"
        : "+f"(c[0]), "+f"(c[1]), "+f"(c[2]), "+f"(c[3])
        : "r"(a0), "r"(a1), "r"(a2), "r"(a3), "r"(b0), "r"(b1));
}

__device__ __forceinline__ uint32_t pack_h2(float lo, float hi) {
    __half2 h = __floats2half2_rn(lo, hi);
    return *(uint32_t*)&h;
}

__device__ __forceinline__ void cp16(void* smem_dst, const void* gmem_src) {
    unsigned a = (unsigned)__cvta_generic_to_shared(smem_dst);
    asm volatile("cp.async.cg.shared.global [%0], [%1], 16;\n" :: "r"(a), "l"(gmem_src));
}

__global__ void __launch_bounds__(NTHREADS, 2)
sdpa_main(const float* __restrict__ Q, float* __restrict__ ctx, float* __restrict__ attn) {
    extern __shared__ __half smh[];
    __half* Kh = smh + KH_OFF;
    __half* Vh = smh + VH_OFF;

    const int qb = blockIdx.x;            // 0..15
    const int bh = blockIdx.y;            // 0..63
    const size_t mrow0 = (size_t)bh * S_LEN + qb * M_BLK;

    const int tid = threadIdx.x, warp = tid >> 5, lane = tid & 31;
    const int g = lane >> 2, t = lane & 3;
    const int r0 = 16 * warp;

    // ---- Q fragments straight from gmem (once) ----
    uint32_t qa[4][4];
    {
        const float* Qp = Q + mrow0 * D_DIM;
#pragma unroll
        for (int kc = 0; kc < 4; kc++) {
            float2 v0 = *(const float2*)(Qp + (r0 + g)     * D_DIM + 16 * kc + 2 * t);
            float2 v1 = *(const float2*)(Qp + (r0 + g + 8) * D_DIM + 16 * kc + 2 * t);
            float2 v2 = *(const float2*)(Qp + (r0 + g)     * D_DIM + 16 * kc + 2 * t + 8);
            float2 v3 = *(const float2*)(Qp + (r0 + g + 8) * D_DIM + 16 * kc + 2 * t + 8);
            qa[kc][0] = pack_h2(v0.x, v0.y);
            qa[kc][1] = pack_h2(v1.x, v1.y);
            qa[kc][2] = pack_h2(v2.x, v2.y);
            qa[kc][3] = pack_h2(v3.x, v3.y);
        }
    }

    const __half* gK = g_Kh + (size_t)bh * S_LEN * D_DIM;
    const __half* gV = g_Vt + (size_t)bh * S_LEN * D_DIM;
#pragma unroll
    for (int j = 0; j < 2; j++) {
        int c = tid + j * NTHREADS;
        int row = c >> 3, off = (c & 7) * 8;
        cp16(&Kh[row * QSH + off], gK + row * D_DIM + off);
        cp16(&Vh[row * QSH + off], gV + row * D_DIM + off);
    }
    asm volatile("cp.async.commit_group;\n");

    const unsigned* mba = g_mbits + (mrow0 + r0 + g) * (S_LEN / 32);
    const unsigned* mbb = mba + 8 * (S_LEN / 32);
    const size_t tb_warp = (((size_t)(bh * 16 + qb) * 8 + warp) * 32) * 512;

    float acc[8][4] = {};
    float rs0 = 0.f, rs1 = 0.f;

    for (int kt = 0; kt < NT; kt++) {
        const int cur = kt & 1, ko = kt * KT;
        __syncthreads();                  // (A)
        if (kt + 1 < NT) {
            __half* kd = Kh + (cur ^ 1) * TILE_H;
            __half* vd = Vh + (cur ^ 1) * TILE_H;
            const __half* ks = gK + (size_t)(ko + KT) * D_DIM;
            const __half* vsrc = gV + (size_t)(ko + KT) * D_DIM;
#pragma unroll
            for (int j = 0; j < 2; j++) {
                int c = tid + j * NTHREADS;
                int row = c >> 3, off = (c & 7) * 8;
                cp16(&kd[row * QSH + off], ks + row * D_DIM + off);
                cp16(&vd[row * QSH + off], vsrc + row * D_DIM + off);
            }
        }
        asm volatile("cp.async.commit_group;\n");
        asm volatile("cp.async.wait_group 1;\n");
        __syncthreads();                  // (B)

        // mask bit-words (broadcast loads)
        const unsigned mwa0 = mba[2 * kt], mwa1 = mba[2 * kt + 1];
        const unsigned mwb0 = mbb[2 * kt], mwb1 = mbb[2 * kt + 1];

        const __half* Kb = Kh + cur * TILE_H;
        const __half* Vb = Vh + cur * TILE_H;

        // ---- QK (nb-outer) + mask + exp + pack ----
        uint32_t pw[16];
        const float scale = 0.125f;
#pragma unroll
        for (int nb = 0; nb < 8; nb++) {
            float cl[4] = {};
#pragma unroll
            for (int kc = 0; kc < 4; kc++) {
                uint32_t b0 = *(const uint32_t*)&Kb[(8 * nb + g) * QSH + 16 * kc + 2 * t];
                uint32_t b1 = *(const uint32_t*)&Kb[(8 * nb + g) * QSH + 16 * kc + 2 * t + 8];
                mma_f16(cl, qa[kc][0], qa[kc][1], qa[kc][2], qa[kc][3], b0, b1);
            }
            const unsigned s = (8 * nb + 2 * t) & 31;
            const unsigned wa = (nb < 4) ? mwa0 : mwa1;
            const unsigned wb = (nb < 4) ? mwb0 : mwb1;
            float e0 = ((wa >> s)       & 1u) ? 0.f : __expf(cl[0] * scale);
            float e1 = ((wa >> (s + 1)) & 1u) ? 0.f : __expf(cl[1] * scale);
            float e2 = ((wb >> s)       & 1u) ? 0.f : __expf(cl[2] * scale);
            float e3 = ((wb >> (s + 1)) & 1u) ? 0.f : __expf(cl[3] * scale);
            rs0 += e0 + e1; rs1 += e2 + e3;
            pw[2 * nb]     = pack_h2(e0, e1);
            pw[2 * nb + 1] = pack_h2(e2, e3);
        }

        // ---- scratch store: [word][lane], 128B coalesced per instruction ----
        {
            uint32_t* sp = g_Eh + tb_warp + (size_t)kt * 512;
#pragma unroll
            for (int w = 0; w < 16; w++)
                sp[w * 32 + lane] = pw[w];
        }

        // ---- PV ----
#pragma unroll
        for (int kc = 0; kc < 4; kc++) {
#pragma unroll
            for (int db = 0; db < 8; db++) {
                uint32_t b0 = *(const uint32_t*)&Vb[(8 * db + g) * QSH + 16 * kc + 2 * t];
                uint32_t b1 = *(const uint32_t*)&Vb[(8 * db + g) * QSH + 16 * kc + 2 * t + 8];
                mma_f16(acc[db], pw[4 * kc], pw[4 * kc + 1], pw[4 * kc + 2], pw[4 * kc + 3], b0, b1);
            }
        }
    }

    // ---- rowsums -> 1/Z ----
    rs0 += __shfl_xor_sync(0xFFFFFFFFu, rs0, 1);
    rs0 += __shfl_xor_sync(0xFFFFFFFFu, rs0, 2);
    rs1 += __shfl_xor_sync(0xFFFFFFFFu, rs1, 1);
    rs1 += __shfl_xor_sync(0xFFFFFFFFu, rs1, 2);
    const float iv0 = 1.f / rs0, iv1 = 1.f / rs1;

    // ---- context = acc / Z (registers) ----
    {
        float* cpa = ctx + (mrow0 + r0 + g) * D_DIM + 2 * t;
        float* cpb = cpa + 8 * D_DIM;
#pragma unroll
        for (int db = 0; db < 8; db++) {
            *(float2*)(cpa + 8 * db) = make_float2(acc[db][0] * iv0, acc[db][1] * iv0);
            *(float2*)(cpb + 8 * db) = make_float2(acc[db][2] * iv1, acc[db][3] * iv1);
        }
    }

    // ---- expand phase: scratch -> normalized fp32 attn, coalesced ----
    __syncthreads();                      // mainloop done with KV smem
    uint32_t* stg = (uint32_t*)smh;       // 8 warps x 544 words (padded transpose)
    float* sinv = (float*)((uint32_t*)smh + 8 * 544);
    if (t == 0) {
        sinv[r0 + g]     = iv0;
        sinv[r0 + g + 8] = iv1;
    }
    __syncthreads();

    const size_t tb_cta = ((size_t)(bh * 16 + qb) * 8) * 32 * 512;
    for (int kt = 0; kt < NT; kt++) {
        // each warp transposes its own tile into padded smem
        const uint32_t* src = g_Eh + tb_cta + (size_t)(warp * 32 + kt) * 512;
#pragma unroll
        for (int k = 0; k < 16; k++)
            stg[warp * 544 + lane * 17 + k] = src[k * 32 + lane];
        __syncthreads();

#pragma unroll
        for (int it = 0; it < 8; it++) {
            int o = it * 256 + tid;       // 0..2047
            int row = o >> 4;             // 0..127
            int cq  = o & 15;
            int wr = row >> 4, r = row & 15, gg = r & 7, p = r >> 3;
            int c0 = cq * 4;
            int nb = c0 >> 3;
            int t0 = (c0 & 7) >> 1;       // 0 or 2
            uint32_t w1 = stg[wr * 544 + (gg * 4 + t0)     * 17 + 2 * nb + p];
            uint32_t w2 = stg[wr * 544 + (gg * 4 + t0 + 1) * 17 + 2 * nb + p];
            float iv = sinv[row];
            __half2 h1 = *(__half2*)&w1, h2 = *(__half2*)&w2;
            float4 out = make_float4(__low2float(h1) * iv, __high2float(h1) * iv,
                                     __low2float(h2) * iv, __high2float(h2) * iv);
            *(float4*)(attn + (mrow0 + row) * S_LEN + kt * KT + c0) = out;
        }
        __syncthreads();
    }
}

extern "C" void kernel_launch(void* const* d_in, const int* in_sizes, int n_in,
                              void* d_out, int out_size) {
    const float* Q = (const float*)d_in[0];
    const float* K = (const float*)d_in[1];
    const float* V = (const float*)d_in[2];
    const unsigned char* M = (const unsigned char*)d_in[3];

    float* ctx  = (float*)d_out;                          // [B,H,S,64]
    float* attn = ctx + (size_t)BH * S_LEN * D_DIM;       // [B,H,S,S]

    cudaFuncSetAttribute(sdpa_main,
                         cudaFuncAttributeMaxDynamicSharedMemorySize, SMEM_BYTES);

    detect_mask_kind<<<1, 256>>>(M);
    mask_bits<<<8192, 256>>>(M);
    convert_k<<<2048, 256>>>(K);
    transpose_v<<<dim3(NT, BH), 256>>>(V);

    dim3 grid(S_LEN / M_BLK, BH);                         // 16 x 64 = 1024 CTAs
    sdpa_main<<<grid, NTHREADS, SMEM_BYTES>>>(Q, ctx, attn);
}